// round 11
// baseline (speedup 1.0000x reference)
#include <cuda_runtime.h>
#include <cuda_bf16.h>
#include <math.h>

#define NU    2560
#define NI    3584
#define NN    6144
#define E     64
#define E2    32
#define DQK   256
#define TOPK  5
#define TOPS  8
#define STRIDE 96

#define KB     192
#define JTHIRD 2048
#define CHUNK  64
#define NCHUNK (JTHIRD / CHUNK)
#define NCAND  (3 * TOPS)
#define APITCH 400
#define BBYTES (CHUNK * APITCH)
#define MPITCH 65           // merge-stage row pitch (bank-spread)

typedef unsigned long long u64;

__device__ float g_ego0[NN * E];
__device__ float g_ego1[NN * E];
__device__ float g_ego2[NN * E];
__device__ float g_z[NN * E];
__device__ float g_Q[NN * DQK];
__device__ float g_K[NN * DQK];
__device__ u64   g_WqT[E2 * DQK];
__device__ u64   g_WkT[E2 * DQK];
__device__ u64   g_WvT[E2 * DQK];
__device__ __align__(16) __nv_bfloat16 g_A[NN * KB];
__device__ __align__(16) __nv_bfloat16 g_B[NN * KB];
__device__ int   g_candi[NN * NCAND];
__device__ int   g_cntN[NN], g_cntA[NN];
__device__ int   g_colN[NN * STRIDE], g_colA[NN * STRIDE];
__device__ float g_valN[NN * STRIDE], g_valA[NN * STRIDE];

__device__ __forceinline__ u64 ffma2(u64 a, u64 b, u64 c) {
    u64 d;
    asm("fma.rn.f32x2 %0, %1, %2, %3;" : "=l"(d) : "l"(a), "l"(b), "l"(c));
    return d;
}
__device__ __forceinline__ float2 up2(u64 v) {
    float2 r;
    asm("mov.b64 {%0, %1}, %2;" : "=f"(r.x), "=f"(r.y) : "l"(v));
    return r;
}
__device__ __forceinline__ unsigned s2u(const void* p) {
    unsigned a;
    asm("{ .reg .u64 t; cvta.to.shared.u64 t, %1; cvt.u32.u64 %0, t; }"
        : "=r"(a) : "l"(p));
    return a;
}
__device__ __forceinline__ void split2(float a, __nv_bfloat16& h, __nv_bfloat16& l) {
    h = __float2bfloat16(a);
    l = __float2bfloat16(a - __bfloat162float(h));
}
__device__ __forceinline__ void top_ins(float v, int j, float* tv, int* ti) {
    if (v > tv[TOPS - 1]) {
        tv[TOPS - 1] = v; ti[TOPS - 1] = j;
#pragma unroll
        for (int q = TOPS - 1; q > 0; q--) {
            if (tv[q] > tv[q - 1]) {
                float fv = tv[q]; tv[q] = tv[q - 1]; tv[q - 1] = fv;
                int fi = ti[q]; ti[q] = ti[q - 1]; ti[q - 1] = fi;
            }
        }
    }
}

// K1: concat + W transpose + padded-ELL placement
__global__ void prep_place_kernel(const float* __restrict__ user,
                                  const float* __restrict__ item,
                                  const int* __restrict__ nr, const int* __restrict__ nc,
                                  const float* __restrict__ nv, int nnzN,
                                  const int* __restrict__ ar, const int* __restrict__ ac,
                                  const float* __restrict__ av, int nnzA,
                                  const float* __restrict__ Wq,
                                  const float* __restrict__ Wk,
                                  const float* __restrict__ Wv) {
    int gid = blockIdx.x * blockDim.x + threadIdx.x;
    const int T1 = NN * E, T2 = T1 + 3 * E2 * DQK, T3 = T2 + nnzN, T4 = T3 + nnzA;
    if (gid < T1) {
        g_ego0[gid] = (gid < NU * E) ? user[gid] : item[gid - NU * E];
    } else if (gid < T2) {
        int idx = gid - T1;
        int m = idx / (E2 * DQK);
        int rem = idx - m * (E2 * DQK);
        int i = rem / DQK, d = rem - (rem / DQK) * DQK;
        const u64* src = (const u64*)(m == 0 ? Wq : (m == 1 ? Wk : Wv));
        u64* dst = (m == 0 ? g_WqT : (m == 1 ? g_WkT : g_WvT));
        dst[i * DQK + d] = src[d * E2 + i];
    } else if (gid < T3) {
        int i = gid - T2;
        int r = nr[i];
        int p = atomicAdd(&g_cntN[r], 1);
        g_colN[r * STRIDE + p] = nc[i];
        g_valN[r * STRIDE + p] = nv[i];
    } else if (gid < T4) {
        int i = gid - T3;
        int r = ar[i];
        int p = atomicAdd(&g_cntA[r], 1);
        g_colA[r * STRIDE + p] = ac[i];
        g_valA[r * STRIDE + p] = av[i];
    }
}

__device__ __forceinline__ float gather_row(const int* __restrict__ cnt,
                                            const int* __restrict__ col,
                                            const float* __restrict__ val,
                                            const float* __restrict__ x,
                                            int r, int e) {
    int j0 = r * STRIDE, j1 = j0 + cnt[r];
    float acc = 0.0f;
    int j = j0;
    for (; j + 8 <= j1; j += 8) {
        int   c[8]; float v[8], xv[8];
#pragma unroll
        for (int u = 0; u < 8; u++) c[u] = __ldg(&col[j + u]);
#pragma unroll
        for (int u = 0; u < 8; u++) v[u] = __ldg(&val[j + u]);
#pragma unroll
        for (int u = 0; u < 8; u++) xv[u] = __ldg(&x[c[u] * E + e]);
#pragma unroll
        for (int u = 0; u < 8; u++) acc += v[u] * xv[u];
    }
    for (; j < j1; j++)
        acc += __ldg(&val[j]) * __ldg(&x[__ldg(&col[j]) * E + e]);
    return acc;
}

// K2: ego1 = A_norm @ ego0
__global__ void __launch_bounds__(256) gather1_kernel() {
    int w = (blockIdx.x * blockDim.x + threadIdx.x) >> 5;
    int e = (w & 1) * 32 + (threadIdx.x & 31);
    int r = w >> 1;
    g_ego1[r * E + e] = gather_row(g_cntN, g_colN, g_valN, g_ego0, r, e);
}

// K3: ego2 = A_norm @ ego1 ; mean out ; B split {eh, el, eh}
__global__ void __launch_bounds__(256) gather2_kernel(float* __restrict__ dout) {
    int w = (blockIdx.x * blockDim.x + threadIdx.x) >> 5;
    int e = (w & 1) * 32 + (threadIdx.x & 31);
    int r = w >> 1;
    float eg2 = gather_row(g_cntN, g_colN, g_valN, g_ego1, r, e);
    g_ego2[r * E + e] = eg2;
    dout[r * E + e] = 0.5f * (g_ego0[r * E + e] + g_ego1[r * E + e]);
    __nv_bfloat16 h, l;
    split2(eg2, h, l);
    __nv_bfloat16* b = &g_B[r * KB + e];
    b[0] = h; b[64] = l; b[128] = h;
}

// K4: z = ego2 + 0.5*A@ego2 ; store z ; A split {zh, zh, zl}
__global__ void __launch_bounds__(256) gatherA_kernel() {
    int w = (blockIdx.x * blockDim.x + threadIdx.x) >> 5;
    int e = (w & 1) * 32 + (threadIdx.x & 31);
    int r = w >> 1;
    float z = 0.5f * gather_row(g_cntA, g_colA, g_valA, g_ego2, r, e)
            + g_ego2[r * E + e];
    g_z[r * E + e] = z;
    __nv_bfloat16 h, l;
    split2(z, h, l);
    __nv_bfloat16* a = &g_A[r * KB + e];
    a[0] = h; a[64] = h; a[128] = l;
}

// K5: Q/K projection (weights in regs) — 192 blocks x 32 rows
__global__ void __launch_bounds__(256, 1) qk_kernel(const float* __restrict__ bq,
                                                    const float* __restrict__ bk) {
    __shared__ u64 xs[32 * E2];
    int t = threadIdx.x;
    u64 wq[E2], wk[E2];
#pragma unroll
    for (int i = 0; i < E2; i++) { wq[i] = g_WqT[i * DQK + t]; wk[i] = g_WkT[i * DQK + t]; }
    float rbq = bq[t], rbk = bk[t];
    const u64* eg = (const u64*)g_ego2;
    int r0 = blockIdx.x * 32;
    for (int i = t; i < 32 * E2; i += 256) xs[i] = eg[r0 * E2 + i];
    __syncthreads();
    for (int rr = 0; rr < 32; rr++) {
        const ulonglong2* xp = (const ulonglong2*)&xs[rr * E2];
        u64 aq = 0ULL, ak = 0ULL;
#pragma unroll
        for (int e2 = 0; e2 < E2; e2 += 2) {
            ulonglong2 xv = xp[e2 >> 1];
            aq = ffma2(wq[e2], xv.x, aq);
            ak = ffma2(wk[e2], xv.x, ak);
            aq = ffma2(wq[e2 + 1], xv.y, aq);
            ak = ffma2(wk[e2 + 1], xv.y, ak);
        }
        float2 q2 = up2(aq), k2 = up2(ak);
        g_Q[(r0 + rr) * DQK + t] = q2.x + q2.y + rbq;
        g_K[(r0 + rr) * DQK + t] = k2.x + k2.y + rbk;
    }
}

// K6: mma.sync bf16 approx sim + per-row top-8 (per j-third)
// Retiled: warp = (row-tile rt = w&3 -> 32 rows, n-half nh = w>>2 -> 32 cols).
// Each warp holds TWO A fragment sets; B ldmatrix count halved vs round 9.
__global__ void __launch_bounds__(256, 1) simtopk_mma_kernel() {
    extern __shared__ char sm[];
    unsigned sA = s2u(sm);
    unsigned sB0 = sA + 128 * APITCH;
    int tid = threadIdx.x, w = tid >> 5, lane = tid & 31;
    int rt = w & 3, nh = w >> 2;
    int rg = blockIdx.x / 3, jthird = blockIdx.x - rg * 3;
    int r0 = rg * 128, jb0 = jthird * JTHIRD;

    {
        unsigned dst = sB0;
        const char* src = (const char*)g_B + (size_t)jb0 * (KB * 2);
        for (int i = tid; i < CHUNK * 24; i += 256) {
            int r = i / 24, c = i - r * 24;
            asm volatile("cp.async.cg.shared.global [%0], [%1], 16;"
                         :: "r"(dst + r * APITCH + c * 16), "l"(src + r * (KB * 2) + c * 16));
        }
        asm volatile("cp.async.commit_group;");
    }
    {
        const u64* asrc = (const u64*)(g_A + (size_t)r0 * KB);
        for (int i = tid; i < 128 * 48; i += 256) {
            int r = i / 48, c = i - r * 48;
            *(u64*)(sm + r * APITCH + c * 8) = asrc[i];
        }
    }
    __syncthreads();

    // two A fragment sets: rows rt*32..+15 and rt*32+16..+31
    unsigned af0[12][4], af1[12][4];
    {
        unsigned ab0 = sA + (rt * 32 + (lane & 15)) * APITCH + ((lane >> 4) << 4);
        unsigned ab1 = ab0 + 16 * APITCH;
#pragma unroll
        for (int kt = 0; kt < 12; kt++) {
            asm volatile("ldmatrix.sync.aligned.m8n8.x4.shared.b16 {%0,%1,%2,%3}, [%4];"
                : "=r"(af0[kt][0]), "=r"(af0[kt][1]), "=r"(af0[kt][2]), "=r"(af0[kt][3])
                : "r"(ab0 + kt * 32));
            asm volatile("ldmatrix.sync.aligned.m8n8.x4.shared.b16 {%0,%1,%2,%3}, [%4];"
                : "=r"(af1[kt][0]), "=r"(af1[kt][1]), "=r"(af1[kt][2]), "=r"(af1[kt][3])
                : "r"(ab1 + kt * 32));
        }
    }

    float tv0[TOPS], tv1[TOPS], tv2[TOPS], tv3[TOPS];
    int   ti0[TOPS], ti1[TOPS], ti2[TOPS], ti3[TOPS];
#pragma unroll
    for (int q = 0; q < TOPS; q++) {
        tv0[q] = tv1[q] = tv2[q] = tv3[q] = -3.0e38f;
        ti0[q] = ti1[q] = ti2[q] = ti3[q] = 0;
    }

    for (int cc = 0; cc < NCHUNK; cc++) {
        if (cc + 1 < NCHUNK) {
            unsigned dst = sB0 + ((cc + 1) & 1) * BBYTES;
            const char* src = (const char*)g_B + (size_t)(jb0 + (cc + 1) * CHUNK) * (KB * 2);
            for (int i = tid; i < CHUNK * 24; i += 256) {
                int r = i / 24, c = i - r * 24;
                asm volatile("cp.async.cg.shared.global [%0], [%1], 16;"
                             :: "r"(dst + r * APITCH + c * 16), "l"(src + r * (KB * 2) + c * 16));
            }
            asm volatile("cp.async.commit_group;");
            asm volatile("cp.async.wait_group 1;");
        } else {
            asm volatile("cp.async.wait_group 0;");
        }
        __syncthreads();
        unsigned sBc = sB0 + (cc & 1) * BBYTES;
        int j0 = jb0 + cc * CHUNK + nh * 32;
#pragma unroll
        for (int nt = 0; nt < 4; nt++) {
            float d0 = 0, d1 = 0, d2 = 0, d3 = 0;
            float e0 = 0, e1 = 0, e2v = 0, e3 = 0;
            unsigned ba = sBc + (nh * 32 + nt * 8 + (lane & 7)) * APITCH
                        + ((lane >> 3) & 1) * 16;
#pragma unroll
            for (int kt = 0; kt < 12; kt++) {
                unsigned p0, p1;
                asm volatile("ldmatrix.sync.aligned.m8n8.x2.shared.b16 {%0,%1}, [%2];"
                             : "=r"(p0), "=r"(p1) : "r"(ba + kt * 32));
                asm volatile("mma.sync.aligned.m16n8k16.row.col.f32.bf16.bf16.f32 "
                    "{%0,%1,%2,%3}, {%4,%5,%6,%7}, {%8,%9}, {%0,%1,%2,%3};"
                    : "+f"(d0), "+f"(d1), "+f"(d2), "+f"(d3)
                    : "r"(af0[kt][0]), "r"(af0[kt][1]), "r"(af0[kt][2]), "r"(af0[kt][3]),
                      "r"(p0), "r"(p1));
                asm volatile("mma.sync.aligned.m16n8k16.row.col.f32.bf16.bf16.f32 "
                    "{%0,%1,%2,%3}, {%4,%5,%6,%7}, {%8,%9}, {%0,%1,%2,%3};"
                    : "+f"(e0), "+f"(e1), "+f"(e2v), "+f"(e3)
                    : "r"(af1[kt][0]), "r"(af1[kt][1]), "r"(af1[kt][2]), "r"(af1[kt][3]),
                      "r"(p0), "r"(p1));
            }
            int jc = j0 + nt * 8 + (lane & 3) * 2;
            top_ins(d0, jc, tv0, ti0);      top_ins(d1, jc + 1, tv0, ti0);
            top_ins(d2, jc, tv1, ti1);      top_ins(d3, jc + 1, tv1, ti1);
            top_ins(e0, jc, tv2, ti2);      top_ins(e1, jc + 1, tv2, ti2);
            top_ins(e2v, jc, tv3, ti3);     top_ins(e3, jc + 1, tv3, ti3);
        }
        __syncthreads();
    }

    // stage: 8 lists per row (2 n-halves x 4 quad-lanes) x top-8 = 64/row
    float* mv = (float*)sm;                         // 128 * 65 * 4 = 33.3 KB
    int*   mi = (int*)(sm + 128 * MPITCH * 4);      // +33.3 KB
    int rbase = rt * 32 + (lane >> 2);
    int sl = (nh * 4 + (lane & 3)) * TOPS;
#pragma unroll
    for (int q = 0; q < TOPS; q++) {
        mv[(rbase)      * MPITCH + sl + q] = tv0[q];  mi[(rbase)      * MPITCH + sl + q] = ti0[q];
        mv[(rbase + 8)  * MPITCH + sl + q] = tv1[q];  mi[(rbase + 8)  * MPITCH + sl + q] = ti1[q];
        mv[(rbase + 16) * MPITCH + sl + q] = tv2[q];  mi[(rbase + 16) * MPITCH + sl + q] = ti2[q];
        mv[(rbase + 24) * MPITCH + sl + q] = tv3[q];  mi[(rbase + 24) * MPITCH + sl + q] = ti3[q];
    }
    __syncthreads();
    if (tid < 128) {
        for (int sel = 0; sel < TOPS; sel++) {
            float best = -3.2e38f; int bs = 0;
            for (int m = 0; m < 64; m++) {
                float vv = mv[tid * MPITCH + m];
                if (vv > best) { best = vv; bs = m; }
            }
            mv[tid * MPITCH + bs] = -3.2e38f;
            g_candi[(r0 + tid) * NCAND + jthird * TOPS + sel] = mi[tid * MPITCH + bs];
        }
    }
}

// K7: exact rescore + top-5 + attention + V proj ; resets ELL counters
// 192 blocks x 32 nodes
__global__ void __launch_bounds__(256, 1) attn_kernel(const float* __restrict__ bv,
                                                      float* __restrict__ out_att) {
    __shared__ __align__(16) float ws[32 * E];
    __shared__ float exv[8][NCAND];
    __shared__ int   exi[8][NCAND];
    int t = threadIdx.x, lane = t & 31, w = t >> 5;
    int n0 = blockIdx.x * 32;

    // reset padded-ELL counters for the next replay
    {
        int i = blockIdx.x * 256 + t;
        if (i < NN) g_cntN[i] = 0;
        else if (i < 2 * NN) g_cntA[i - NN] = 0;
    }

    for (int i = 0; i < 4; i++) {
        int nl = i * 8 + w;
        int n = n0 + nl;
        int cid = g_candi[n * NCAND + (lane < NCAND ? lane : 0)];
        if (lane < NCAND) exi[w][lane] = cid;
        float zl0 = g_z[n * E + lane];
        float zl1 = g_z[n * E + lane + 32];
#pragma unroll
        for (int m = 0; m < NCAND; m++) {
            int id = __shfl_sync(0xffffffffu, cid, m);
            const float* ep = &g_ego2[id * E];
            float s = zl0 * ep[lane] + zl1 * ep[lane + 32];
#pragma unroll
            for (int o = 16; o > 0; o >>= 1)
                s += __shfl_xor_sync(0xffffffffu, s, o);
            if (lane == 0) exv[w][m] = s;
        }
        __syncwarp();
        int idx[TOPK];
        for (int sel = 0; sel < TOPK; sel++) {
            float best = -3.2e38f; int bs = 0;
#pragma unroll
            for (int m = 0; m < NCAND; m++) {
                float vv = exv[w][m];
                if (vv > best) { best = vv; bs = m; }
            }
            idx[sel] = exi[w][bs];
            __syncwarp();
            if (lane == 0) exv[w][bs] = -3.2e38f;
            __syncwarp();
        }
        float q[8];
#pragma unroll
        for (int j = 0; j < 8; j++) q[j] = g_Q[n * DQK + j * 32 + lane];
        float p[TOPK];
#pragma unroll
        for (int k = 0; k < TOPK; k++) {
            const float* kp = &g_K[idx[k] * DQK];
            float s = 0.0f;
#pragma unroll
            for (int j = 0; j < 8; j++) s += q[j] * kp[j * 32 + lane];
            p[k] = s;
        }
#pragma unroll
        for (int k = 0; k < TOPK; k++)
#pragma unroll
            for (int o = 16; o > 0; o >>= 1)
                p[k] += __shfl_xor_sync(0xffffffffu, p[k], o);
        float mx = -3.0e38f;
#pragma unroll
        for (int k = 0; k < TOPK; k++) { p[k] *= 0.0625f; mx = fmaxf(mx, p[k]); }
        float den = 0.0f;
#pragma unroll
        for (int k = 0; k < TOPK; k++) { p[k] = __expf(p[k] - mx); den += p[k]; }
        float inv = 1.0f / den;
        float a0 = 0.0f, a1 = 0.0f;
#pragma unroll
        for (int k = 0; k < TOPK; k++) {
            float a = p[k] * inv;
            const float* ep = &g_ego2[idx[k] * E];
            a0 += a * ep[lane];
            a1 += a * ep[lane + 32];
        }
        ws[nl * E + lane] = a0;
        ws[nl * E + lane + 32] = a1;
    }
    __syncthreads();
    u64 wv[E2];
#pragma unroll
    for (int i = 0; i < E2; i++) wv[i] = g_WvT[i * DQK + t];
    float rbv = bv[t];
    for (int rr = 0; rr < 32; rr++) {
        const ulonglong2* xp = (const ulonglong2*)&ws[rr * E];
        u64 av = 0ULL;
#pragma unroll
        for (int e2 = 0; e2 < E2; e2 += 2) {
            ulonglong2 xv = xp[e2 >> 1];
            av = ffma2(wv[e2], xv.x, av);
            av = ffma2(wv[e2 + 1], xv.y, av);
        }
        float2 fv = up2(av);
        out_att[(n0 + rr) * DQK + t] = fv.x + fv.y + rbv;
    }
}

extern "C" void kernel_launch(void* const* d_in, const int* in_sizes, int n_in,
                              void* d_out, int out_size) {
    const float* user = (const float*)d_in[0];
    const float* item = (const float*)d_in[1];
    const int* nr = (const int*)d_in[2];
    const int* nc = (const int*)d_in[3];
    const float* nv = (const float*)d_in[4];
    const int* ar = (const int*)d_in[5];
    const int* ac = (const int*)d_in[6];
    const float* av = (const float*)d_in[7];
    const float* Wq = (const float*)d_in[8];
    const float* bq = (const float*)d_in[9];
    const float* Wk = (const float*)d_in[10];
    const float* bk = (const float*)d_in[11];
    const float* Wv = (const float*)d_in[12];
    const float* bv = (const float*)d_in[13];
    int nnzN = in_sizes[2];
    int nnzA = in_sizes[5];
    float* out = (float*)d_out;

    const int TPB = 256;
    int total1 = NN * E + 3 * E2 * DQK + nnzN + nnzA;
    prep_place_kernel<<<(total1 + TPB - 1) / TPB, TPB>>>(
        user, item, nr, nc, nv, nnzN, ar, ac, av, nnzA, Wq, Wk, Wv);

    int gridG = (NN * 64) / TPB;
    gather1_kernel<<<gridG, TPB>>>();
    gather2_kernel<<<gridG, TPB>>>(out);
    gatherA_kernel<<<gridG, TPB>>>();
    qk_kernel<<<NN / 32, TPB>>>(bq, bk);

    int smem_mma = 128 * APITCH + 2 * BBYTES;   // 102400
    cudaFuncSetAttribute(simtopk_mma_kernel,
                         cudaFuncAttributeMaxDynamicSharedMemorySize, smem_mma);
    simtopk_mma_kernel<<<(NN / 128) * 3, TPB, smem_mma>>>();

    attn_kernel<<<NN / 32, TPB>>>(bv, out + NN * E);
}

// round 12
// speedup vs baseline: 1.0080x; 1.0080x over previous
#include <cuda_runtime.h>
#include <cuda_fp16.h>
#include <math.h>

#define NU    2560
#define NI    3584
#define NN    6144
#define E     64
#define E2    32
#define DQK   256
#define TOPK  5
#define TOPS  10
#define STRIDE 96

#define KB     128          // fp16 split K: 2 segments of 64
#define JTHIRD 2048
#define CHUNK  64
#define NCHUNK (JTHIRD / CHUNK)
#define NCAND  (3 * TOPS)   // 30
#define APITCH 272          // 256B row + 16B pad (conflict-free ldmatrix)
#define BBYTES (CHUNK * APITCH)
#define MPITCH 41           // merge row pitch (40 cands + 1 pad)

typedef unsigned long long u64;

__device__ float g_ego0[NN * E];
__device__ float g_ego1[NN * E];
__device__ float g_ego2[NN * E];
__device__ float g_z[NN * E];
__device__ float g_Q[NN * DQK];
__device__ float g_K[NN * DQK];
__device__ u64   g_WqT[E2 * DQK];
__device__ u64   g_WkT[E2 * DQK];
__device__ u64   g_WvT[E2 * DQK];
__device__ __align__(16) __half g_A[NN * KB];
__device__ __align__(16) __half g_B[NN * KB];
__device__ int   g_candi[NN * NCAND];
__device__ int   g_cntN[NN], g_cntA[NN];
__device__ int   g_colN[NN * STRIDE], g_colA[NN * STRIDE];
__device__ float g_valN[NN * STRIDE], g_valA[NN * STRIDE];

__device__ __forceinline__ u64 ffma2(u64 a, u64 b, u64 c) {
    u64 d;
    asm("fma.rn.f32x2 %0, %1, %2, %3;" : "=l"(d) : "l"(a), "l"(b), "l"(c));
    return d;
}
__device__ __forceinline__ float2 up2(u64 v) {
    float2 r;
    asm("mov.b64 {%0, %1}, %2;" : "=f"(r.x), "=f"(r.y) : "l"(v));
    return r;
}
__device__ __forceinline__ unsigned s2u(const void* p) {
    unsigned a;
    asm("{ .reg .u64 t; cvta.to.shared.u64 t, %1; cvt.u32.u64 %0, t; }"
        : "=r"(a) : "l"(p));
    return a;
}
__device__ __forceinline__ void split2h(float a, __half& h, __half& l) {
    h = __float2half_rn(a);
    l = __float2half_rn(a - __half2float(h));
}
__device__ __forceinline__ void top_ins(float v, int j, float* tv, int* ti) {
    if (v > tv[TOPS - 1]) {
        tv[TOPS - 1] = v; ti[TOPS - 1] = j;
#pragma unroll
        for (int q = TOPS - 1; q > 0; q--) {
            if (tv[q] > tv[q - 1]) {
                float fv = tv[q]; tv[q] = tv[q - 1]; tv[q - 1] = fv;
                int fi = ti[q]; ti[q] = ti[q - 1]; ti[q - 1] = fi;
            }
        }
    }
}

// K1: concat + W transpose + padded-ELL placement
__global__ void prep_place_kernel(const float* __restrict__ user,
                                  const float* __restrict__ item,
                                  const int* __restrict__ nr, const int* __restrict__ nc,
                                  const float* __restrict__ nv, int nnzN,
                                  const int* __restrict__ ar, const int* __restrict__ ac,
                                  const float* __restrict__ av, int nnzA,
                                  const float* __restrict__ Wq,
                                  const float* __restrict__ Wk,
                                  const float* __restrict__ Wv) {
    int gid = blockIdx.x * blockDim.x + threadIdx.x;
    const int T1 = NN * E, T2 = T1 + 3 * E2 * DQK, T3 = T2 + nnzN, T4 = T3 + nnzA;
    if (gid < T1) {
        g_ego0[gid] = (gid < NU * E) ? user[gid] : item[gid - NU * E];
    } else if (gid < T2) {
        int idx = gid - T1;
        int m = idx / (E2 * DQK);
        int rem = idx - m * (E2 * DQK);
        int i = rem / DQK, d = rem - (rem / DQK) * DQK;
        const u64* src = (const u64*)(m == 0 ? Wq : (m == 1 ? Wk : Wv));
        u64* dst = (m == 0 ? g_WqT : (m == 1 ? g_WkT : g_WvT));
        dst[i * DQK + d] = src[d * E2 + i];
    } else if (gid < T3) {
        int i = gid - T2;
        int r = nr[i];
        int p = atomicAdd(&g_cntN[r], 1);
        g_colN[r * STRIDE + p] = nc[i];
        g_valN[r * STRIDE + p] = nv[i];
    } else if (gid < T4) {
        int i = gid - T3;
        int r = ar[i];
        int p = atomicAdd(&g_cntA[r], 1);
        g_colA[r * STRIDE + p] = ac[i];
        g_valA[r * STRIDE + p] = av[i];
    }
}

__device__ __forceinline__ float gather_row(const int* __restrict__ cnt,
                                            const int* __restrict__ col,
                                            const float* __restrict__ val,
                                            const float* __restrict__ x,
                                            int r, int e) {
    int j0 = r * STRIDE, j1 = j0 + cnt[r];
    float acc = 0.0f;
    int j = j0;
    for (; j + 8 <= j1; j += 8) {
        int   c[8]; float v[8], xv[8];
#pragma unroll
        for (int u = 0; u < 8; u++) c[u] = __ldg(&col[j + u]);
#pragma unroll
        for (int u = 0; u < 8; u++) v[u] = __ldg(&val[j + u]);
#pragma unroll
        for (int u = 0; u < 8; u++) xv[u] = __ldg(&x[c[u] * E + e]);
#pragma unroll
        for (int u = 0; u < 8; u++) acc += v[u] * xv[u];
    }
    for (; j < j1; j++)
        acc += __ldg(&val[j]) * __ldg(&x[__ldg(&col[j]) * E + e]);
    return acc;
}

// K2: ego1 = A_norm @ ego0
__global__ void __launch_bounds__(256) gather1_kernel() {
    int w = (blockIdx.x * blockDim.x + threadIdx.x) >> 5;
    int e = (w & 1) * 32 + (threadIdx.x & 31);
    int r = w >> 1;
    g_ego1[r * E + e] = gather_row(g_cntN, g_colN, g_valN, g_ego0, r, e);
}

// K3: ego2 = A_norm @ ego1 ; mean out ; B split {eh, el}
__global__ void __launch_bounds__(256) gather2_kernel(float* __restrict__ dout) {
    int w = (blockIdx.x * blockDim.x + threadIdx.x) >> 5;
    int e = (w & 1) * 32 + (threadIdx.x & 31);
    int r = w >> 1;
    float eg2 = gather_row(g_cntN, g_colN, g_valN, g_ego1, r, e);
    g_ego2[r * E + e] = eg2;
    dout[r * E + e] = 0.5f * (g_ego0[r * E + e] + g_ego1[r * E + e]);
    __half h, l;
    split2h(eg2, h, l);
    __half* b = &g_B[r * KB + e];
    b[0] = h; b[64] = l;
}

// K4: z = ego2 + 0.5*A@ego2 ; store z ; A split {zh, zh}
__global__ void __launch_bounds__(256) gatherA_kernel() {
    int w = (blockIdx.x * blockDim.x + threadIdx.x) >> 5;
    int e = (w & 1) * 32 + (threadIdx.x & 31);
    int r = w >> 1;
    float z = 0.5f * gather_row(g_cntA, g_colA, g_valA, g_ego2, r, e)
            + g_ego2[r * E + e];
    g_z[r * E + e] = z;
    __half h = __float2half_rn(z);
    __half* a = &g_A[r * KB + e];
    a[0] = h; a[64] = h;
}

// K5: Q/K projection (weights in regs) — 192 blocks x 32 rows
__global__ void __launch_bounds__(256, 1) qk_kernel(const float* __restrict__ bq,
                                                    const float* __restrict__ bk) {
    __shared__ u64 xs[32 * E2];
    int t = threadIdx.x;
    u64 wq[E2], wk[E2];
#pragma unroll
    for (int i = 0; i < E2; i++) { wq[i] = g_WqT[i * DQK + t]; wk[i] = g_WkT[i * DQK + t]; }
    float rbq = bq[t], rbk = bk[t];
    const u64* eg = (const u64*)g_ego2;
    int r0 = blockIdx.x * 32;
    for (int i = t; i < 32 * E2; i += 256) xs[i] = eg[r0 * E2 + i];
    __syncthreads();
    for (int rr = 0; rr < 32; rr++) {
        const ulonglong2* xp = (const ulonglong2*)&xs[rr * E2];
        u64 aq = 0ULL, ak = 0ULL;
#pragma unroll
        for (int e2 = 0; e2 < E2; e2 += 2) {
            ulonglong2 xv = xp[e2 >> 1];
            aq = ffma2(wq[e2], xv.x, aq);
            ak = ffma2(wk[e2], xv.x, ak);
            aq = ffma2(wq[e2 + 1], xv.y, aq);
            ak = ffma2(wk[e2 + 1], xv.y, ak);
        }
        float2 q2 = up2(aq), k2 = up2(ak);
        g_Q[(r0 + rr) * DQK + t] = q2.x + q2.y + rbq;
        g_K[(r0 + rr) * DQK + t] = k2.x + k2.y + rbk;
    }
}

// K6: mma.sync fp16 approx sim (K=128) + per-row top-10 (per j-third)
// R10-proven tiling: warp w -> rows w*16..+15, full 64-col range.
__global__ void __launch_bounds__(256, 1) simtopk_mma_kernel() {
    extern __shared__ char sm[];
    unsigned sA = s2u(sm);
    unsigned sB0 = sA + 128 * APITCH;
    int tid = threadIdx.x, w = tid >> 5, lane = tid & 31;
    int rg = blockIdx.x / 3, jthird = blockIdx.x - rg * 3;
    int r0 = rg * 128, jb0 = jthird * JTHIRD;

    // B chunk 0 via cp.async (overlaps A fill). Row = 256B = 16 x 16B.
    {
        unsigned dst = sB0;
        const char* src = (const char*)g_B + (size_t)jb0 * (KB * 2);
        for (int i = tid; i < CHUNK * 16; i += 256) {
            int r = i >> 4, c = i & 15;
            asm volatile("cp.async.cg.shared.global [%0], [%1], 16;"
                         :: "r"(dst + r * APITCH + c * 16), "l"(src + r * (KB * 2) + c * 16));
        }
        asm volatile("cp.async.commit_group;");
    }
    // A tile fill: 128 rows x 32 u64, pitch 272
    {
        const u64* asrc = (const u64*)(g_A + (size_t)r0 * KB);
        for (int i = tid; i < 128 * 32; i += 256) {
            int r = i >> 5, c = i & 31;
            *(u64*)(sm + r * APITCH + c * 8) = asrc[i];
        }
    }
    __syncthreads();

    // A fragments: 8 k-tiles of m16k16 per warp
    unsigned af[8][4];
    {
        unsigned ab = sA + (w * 16 + (lane & 15)) * APITCH + ((lane >> 4) << 4);
#pragma unroll
        for (int kt = 0; kt < 8; kt++)
            asm volatile("ldmatrix.sync.aligned.m8n8.x4.shared.b16 {%0,%1,%2,%3}, [%4];"
                : "=r"(af[kt][0]), "=r"(af[kt][1]), "=r"(af[kt][2]), "=r"(af[kt][3])
                : "r"(ab + kt * 32));
    }

    float tv0[TOPS], tv1[TOPS]; int ti0[TOPS], ti1[TOPS];
#pragma unroll
    for (int q = 0; q < TOPS; q++) {
        tv0[q] = -3.0e38f; tv1[q] = -3.0e38f; ti0[q] = 0; ti1[q] = 0;
    }

    for (int cc = 0; cc < NCHUNK; cc++) {
        if (cc + 1 < NCHUNK) {
            unsigned dst = sB0 + ((cc + 1) & 1) * BBYTES;
            const char* src = (const char*)g_B + (size_t)(jb0 + (cc + 1) * CHUNK) * (KB * 2);
            for (int i = tid; i < CHUNK * 16; i += 256) {
                int r = i >> 4, c = i & 15;
                asm volatile("cp.async.cg.shared.global [%0], [%1], 16;"
                             :: "r"(dst + r * APITCH + c * 16), "l"(src + r * (KB * 2) + c * 16));
            }
            asm volatile("cp.async.commit_group;");
            asm volatile("cp.async.wait_group 1;");
        } else {
            asm volatile("cp.async.wait_group 0;");
        }
        __syncthreads();
        unsigned sBc = sB0 + (cc & 1) * BBYTES;
        int j0 = jb0 + cc * CHUNK;
        for (int jt = 0; jt < 8; jt += 2) {
            float dA0 = 0, dA1 = 0, dA2 = 0, dA3 = 0;
            float dB0 = 0, dB1 = 0, dB2 = 0, dB3 = 0;
            unsigned ba = sBc + (jt * 8 + (lane & 7)) * APITCH + ((lane >> 3) & 1) * 16;
            unsigned bb = ba + 8 * APITCH;
#pragma unroll
            for (int kt = 0; kt < 8; kt++) {
                unsigned p0, p1, q0, q1;
                asm volatile("ldmatrix.sync.aligned.m8n8.x2.shared.b16 {%0,%1}, [%2];"
                             : "=r"(p0), "=r"(p1) : "r"(ba + kt * 32));
                asm volatile("ldmatrix.sync.aligned.m8n8.x2.shared.b16 {%0,%1}, [%2];"
                             : "=r"(q0), "=r"(q1) : "r"(bb + kt * 32));
                asm volatile("mma.sync.aligned.m16n8k16.row.col.f32.f16.f16.f32 "
                    "{%0,%1,%2,%3}, {%4,%5,%6,%7}, {%8,%9}, {%0,%1,%2,%3};"
                    : "+f"(dA0), "+f"(dA1), "+f"(dA2), "+f"(dA3)
                    : "r"(af[kt][0]), "r"(af[kt][1]), "r"(af[kt][2]), "r"(af[kt][3]),
                      "r"(p0), "r"(p1));
                asm volatile("mma.sync.aligned.m16n8k16.row.col.f32.f16.f16.f32 "
                    "{%0,%1,%2,%3}, {%4,%5,%6,%7}, {%8,%9}, {%0,%1,%2,%3};"
                    : "+f"(dB0), "+f"(dB1), "+f"(dB2), "+f"(dB3)
                    : "r"(af[kt][0]), "r"(af[kt][1]), "r"(af[kt][2]), "r"(af[kt][3]),
                      "r"(q0), "r"(q1));
            }
            int jcA = j0 + jt * 8 + (lane & 3) * 2;
            int jcB = jcA + 8;
            top_ins(dA0, jcA, tv0, ti0);     top_ins(dA1, jcA + 1, tv0, ti0);
            top_ins(dA2, jcA, tv1, ti1);     top_ins(dA3, jcA + 1, tv1, ti1);
            top_ins(dB0, jcB, tv0, ti0);     top_ins(dB1, jcB + 1, tv0, ti0);
            top_ins(dB2, jcB, tv1, ti1);     top_ins(dB3, jcB + 1, tv1, ti1);
        }
        __syncthreads();
    }

    // merge: 4 quad-lanes per row x top-10 = 40 per row (reuse smem)
    float* mv = (float*)sm;
    int*   mi = (int*)(sm + 128 * MPITCH * 4);
    int rb = w * 16 + (lane >> 2);
    int slot = (lane & 3) * TOPS;
#pragma unroll
    for (int q = 0; q < TOPS; q++) {
        mv[rb * MPITCH + slot + q] = tv0[q];        mi[rb * MPITCH + slot + q] = ti0[q];
        mv[(rb + 8) * MPITCH + slot + q] = tv1[q];  mi[(rb + 8) * MPITCH + slot + q] = ti1[q];
    }
    __syncthreads();
    if (tid < 128) {
        for (int sel = 0; sel < TOPS; sel++) {
            float best = -3.2e38f; int bs = 0;
            for (int m = 0; m < 40; m++) {
                float vv = mv[tid * MPITCH + m];
                if (vv > best) { best = vv; bs = m; }
            }
            mv[tid * MPITCH + bs] = -3.2e38f;
            g_candi[(r0 + tid) * NCAND + jthird * TOPS + sel] = mi[tid * MPITCH + bs];
        }
    }
}

// K7: exact rescore of 30 candidates + top-5 + attention + V proj
// 192 blocks x 32 nodes; resets ELL counters for replay.
__global__ void __launch_bounds__(256, 1) attn_kernel(const float* __restrict__ bv,
                                                      float* __restrict__ out_att) {
    __shared__ __align__(16) float ws[32 * E];
    __shared__ float exv[8][NCAND];
    __shared__ int   exi[8][NCAND];
    int t = threadIdx.x, lane = t & 31, w = t >> 5;
    int n0 = blockIdx.x * 32;

    {
        int i = blockIdx.x * 256 + t;
        if (i < NN) g_cntN[i] = 0;
        else if (i < 2 * NN) g_cntA[i - NN] = 0;
    }

    for (int i = 0; i < 4; i++) {
        int nl = i * 8 + w;
        int n = n0 + nl;
        int cid = g_candi[n * NCAND + (lane < NCAND ? lane : 0)];
        if (lane < NCAND) exi[w][lane] = cid;
        float zl0 = g_z[n * E + lane];
        float zl1 = g_z[n * E + lane + 32];
#pragma unroll
        for (int m = 0; m < NCAND; m++) {
            int id = __shfl_sync(0xffffffffu, cid, m);
            const float* ep = &g_ego2[id * E];
            float s = zl0 * ep[lane] + zl1 * ep[lane + 32];
#pragma unroll
            for (int o = 16; o > 0; o >>= 1)
                s += __shfl_xor_sync(0xffffffffu, s, o);
            if (lane == 0) exv[w][m] = s;
        }
        __syncwarp();
        int idx[TOPK];
        for (int sel = 0; sel < TOPK; sel++) {
            float best = -3.2e38f; int bs = 0;
#pragma unroll
            for (int m = 0; m < NCAND; m++) {
                float vv = exv[w][m];
                if (vv > best) { best = vv; bs = m; }
            }
            idx[sel] = exi[w][bs];
            __syncwarp();
            if (lane == 0) exv[w][bs] = -3.2e38f;
            __syncwarp();
        }
        float q[8];
#pragma unroll
        for (int j = 0; j < 8; j++) q[j] = g_Q[n * DQK + j * 32 + lane];
        float p[TOPK];
#pragma unroll
        for (int k = 0; k < TOPK; k++) {
            const float* kp = &g_K[idx[k] * DQK];
            float s = 0.0f;
#pragma unroll
            for (int j = 0; j < 8; j++) s += q[j] * kp[j * 32 + lane];
            p[k] = s;
        }
#pragma unroll
        for (int k = 0; k < TOPK; k++)
#pragma unroll
            for (int o = 16; o > 0; o >>= 1)
                p[k] += __shfl_xor_sync(0xffffffffu, p[k], o);
        float mx = -3.0e38f;
#pragma unroll
        for (int k = 0; k < TOPK; k++) { p[k] *= 0.0625f; mx = fmaxf(mx, p[k]); }
        float den = 0.0f;
#pragma unroll
        for (int k = 0; k < TOPK; k++) { p[k] = __expf(p[k] - mx); den += p[k]; }
        float inv = 1.0f / den;
        float a0 = 0.0f, a1 = 0.0f;
#pragma unroll
        for (int k = 0; k < TOPK; k++) {
            float a = p[k] * inv;
            const float* ep = &g_ego2[idx[k] * E];
            a0 += a * ep[lane];
            a1 += a * ep[lane + 32];
        }
        ws[nl * E + lane] = a0;
        ws[nl * E + lane + 32] = a1;
    }
    __syncthreads();
    u64 wv[E2];
#pragma unroll
    for (int i = 0; i < E2; i++) wv[i] = g_WvT[i * DQK + t];
    float rbv = bv[t];
    for (int rr = 0; rr < 32; rr++) {
        const ulonglong2* xp = (const ulonglong2*)&ws[rr * E];
        u64 av = 0ULL;
#pragma unroll
        for (int e2 = 0; e2 < E2; e2 += 2) {
            ulonglong2 xv = xp[e2 >> 1];
            av = ffma2(wv[e2], xv.x, av);
            av = ffma2(wv[e2 + 1], xv.y, av);
        }
        float2 fv = up2(av);
        out_att[(n0 + rr) * DQK + t] = fv.x + fv.y + rbv;
    }
}

extern "C" void kernel_launch(void* const* d_in, const int* in_sizes, int n_in,
                              void* d_out, int out_size) {
    const float* user = (const float*)d_in[0];
    const float* item = (const float*)d_in[1];
    const int* nr = (const int*)d_in[2];
    const int* nc = (const int*)d_in[3];
    const float* nv = (const float*)d_in[4];
    const int* ar = (const int*)d_in[5];
    const int* ac = (const int*)d_in[6];
    const float* av = (const float*)d_in[7];
    const float* Wq = (const float*)d_in[8];
    const float* bq = (const float*)d_in[9];
    const float* Wk = (const float*)d_in[10];
    const float* bk = (const float*)d_in[11];
    const float* Wv = (const float*)d_in[12];
    const float* bv = (const float*)d_in[13];
    int nnzN = in_sizes[2];
    int nnzA = in_sizes[5];
    float* out = (float*)d_out;

    const int TPB = 256;
    int total1 = NN * E + 3 * E2 * DQK + nnzN + nnzA;
    prep_place_kernel<<<(total1 + TPB - 1) / TPB, TPB>>>(
        user, item, nr, nc, nv, nnzN, ar, ac, av, nnzA, Wq, Wk, Wv);

    int gridG = (NN * 64) / TPB;
    gather1_kernel<<<gridG, TPB>>>();
    gather2_kernel<<<gridG, TPB>>>(out);
    gatherA_kernel<<<gridG, TPB>>>();
    qk_kernel<<<NN / 32, TPB>>>(bq, bk);

    int smem_mma = 128 * APITCH + 2 * BBYTES;   // 34816 + 34816 = 69632
    cudaFuncSetAttribute(simtopk_mma_kernel,
                         cudaFuncAttributeMaxDynamicSharedMemorySize, smem_mma);
    simtopk_mma_kernel<<<(NN / 128) * 3, TPB, smem_mma>>>();

    attn_kernel<<<NN / 32, TPB>>>(bv, out + NN * E);
}

// round 13
// speedup vs baseline: 1.0092x; 1.0012x over previous
#include <cuda_runtime.h>
#include <cuda_fp16.h>
#include <math.h>

#define NU    2560
#define NI    3584
#define NN    6144
#define E     64
#define E2    32
#define DQK   256
#define TOPK  5
#define TOPS  10
#define STRIDE 96

#define KB     128          // fp16 split K: 2 segments of 64
#define JTHIRD 2048
#define CHUNK  64
#define NCHUNK (JTHIRD / CHUNK)
#define NCAND  (3 * TOPS)   // 30
#define APITCH 272
#define BBYTES (CHUNK * APITCH)
#define MPITCH 41

typedef unsigned long long u64;

__device__ float g_ego0[NN * E];
__device__ float g_ego1[NN * E];
__device__ float g_ego2[NN * E];
__device__ float g_z[NN * E];
__device__ float g_Q[NN * DQK];
__device__ float g_K[NN * DQK];
__device__ u64   g_WqT[E2 * DQK];
__device__ u64   g_WkT[E2 * DQK];
__device__ u64   g_WvT[E2 * DQK];
__device__ __align__(16) __half g_A[NN * KB];
__device__ __align__(16) __half g_B[NN * KB];
__device__ int   g_candi[NN * NCAND];
__device__ int   g_cntN[NN], g_cntA[NN];
__device__ int2  g_ellN[NN * STRIDE], g_ellA[NN * STRIDE];

__device__ __forceinline__ u64 ffma2(u64 a, u64 b, u64 c) {
    u64 d;
    asm("fma.rn.f32x2 %0, %1, %2, %3;" : "=l"(d) : "l"(a), "l"(b), "l"(c));
    return d;
}
__device__ __forceinline__ float2 up2(u64 v) {
    float2 r;
    asm("mov.b64 {%0, %1}, %2;" : "=f"(r.x), "=f"(r.y) : "l"(v));
    return r;
}
__device__ __forceinline__ unsigned s2u(const void* p) {
    unsigned a;
    asm("{ .reg .u64 t; cvta.to.shared.u64 t, %1; cvt.u32.u64 %0, t; }"
        : "=r"(a) : "l"(p));
    return a;
}
__device__ __forceinline__ void split2h(float a, __half& h, __half& l) {
    h = __float2half_rn(a);
    l = __float2half_rn(a - __half2float(h));
}
__device__ __forceinline__ void top_ins(float v, int j, float* tv, int* ti) {
    if (v > tv[TOPS - 1]) {
        tv[TOPS - 1] = v; ti[TOPS - 1] = j;
#pragma unroll
        for (int q = TOPS - 1; q > 0; q--) {
            if (tv[q] > tv[q - 1]) {
                float fv = tv[q]; tv[q] = tv[q - 1]; tv[q - 1] = fv;
                int fi = ti[q]; ti[q] = ti[q - 1]; ti[q - 1] = fi;
            }
        }
    }
}

// K1: concat + W transpose + padded-ELL placement (int2-packed)
__global__ void prep_place_kernel(const float* __restrict__ user,
                                  const float* __restrict__ item,
                                  const int* __restrict__ nr, const int* __restrict__ nc,
                                  const float* __restrict__ nv, int nnzN,
                                  const int* __restrict__ ar, const int* __restrict__ ac,
                                  const float* __restrict__ av, int nnzA,
                                  const float* __restrict__ Wq,
                                  const float* __restrict__ Wk,
                                  const float* __restrict__ Wv) {
    int gid = blockIdx.x * blockDim.x + threadIdx.x;
    const int T1 = NN * E, T2 = T1 + 3 * E2 * DQK, T3 = T2 + nnzN, T4 = T3 + nnzA;
    if (gid < T1) {
        g_ego0[gid] = (gid < NU * E) ? user[gid] : item[gid - NU * E];
    } else if (gid < T2) {
        int idx = gid - T1;
        int m = idx / (E2 * DQK);
        int rem = idx - m * (E2 * DQK);
        int i = rem / DQK, d = rem - (rem / DQK) * DQK;
        const u64* src = (const u64*)(m == 0 ? Wq : (m == 1 ? Wk : Wv));
        u64* dst = (m == 0 ? g_WqT : (m == 1 ? g_WkT : g_WvT));
        dst[i * DQK + d] = src[d * E2 + i];
    } else if (gid < T3) {
        int i = gid - T2;
        int r = nr[i];
        int p = atomicAdd(&g_cntN[r], 1);
        g_ellN[r * STRIDE + p] = make_int2(nc[i], __float_as_int(nv[i]));
    } else if (gid < T4) {
        int i = gid - T3;
        int r = ar[i];
        int p = atomicAdd(&g_cntA[r], 1);
        g_ellA[r * STRIDE + p] = make_int2(ac[i], __float_as_int(av[i]));
    }
}

// partial gather over [j0, j1) of the int2 ELL
__device__ __forceinline__ float gather_part(const int2* __restrict__ ell,
                                             int j0, int j1,
                                             const float* __restrict__ x, int e) {
    float acc = 0.0f;
    int j = j0;
    for (; j + 8 <= j1; j += 8) {
        int2 cv[8]; float xv[8];
#pragma unroll
        for (int u = 0; u < 8; u++) cv[u] = __ldg(&ell[j + u]);
#pragma unroll
        for (int u = 0; u < 8; u++) xv[u] = __ldg(&x[cv[u].x * E + e]);
#pragma unroll
        for (int u = 0; u < 8; u++) acc += __int_as_float(cv[u].y) * xv[u];
    }
    for (; j < j1; j++) {
        int2 cv = __ldg(&ell[j]);
        acc += __int_as_float(cv.y) * __ldg(&x[cv.x * E + e]);
    }
    return acc;
}

// split-gather skeleton: block = 2 rows x 4 warps (e-half x j-half).
// Returns full row sum for warps with sub<2; others return garbage (unused).
// part[] must be __shared__ float [2][64].
__device__ __forceinline__ float gather_split(const int* __restrict__ cnt,
                                              const int2* __restrict__ ell,
                                              const float* __restrict__ x,
                                              float (*part)[64],
                                              int r, int rloc, int sub, int e) {
    int c = cnt[r];
    int h = (c >> 1) & ~7;      // jlo gets h (multiple of 8), jhi the rest
    int base = r * STRIDE;
    int jhalf = sub >> 1;
    int j0 = base + (jhalf ? h : 0);
    int j1 = base + (jhalf ? c : h);
    float acc = gather_part(ell, j0, j1, x, e);
    if (jhalf) part[rloc][e] = acc;
    __syncthreads();
    if (!jhalf) acc += part[rloc][e];
    return acc;
}

// K2: ego1 = A_norm @ ego0  (3072 blocks x 2 rows)
__global__ void __launch_bounds__(256) gather1_kernel() {
    __shared__ float part[2][64];
    int w = threadIdx.x >> 5, lane = threadIdx.x & 31;
    int rloc = w >> 2, sub = w & 3;
    int r = blockIdx.x * 2 + rloc;
    int e = (sub & 1) * 32 + lane;
    float acc = gather_split(g_cntN, g_ellN, g_ego0, part, r, rloc, sub, e);
    if (!(sub >> 1)) g_ego1[r * E + e] = acc;
}

// K3: ego2 = A_norm @ ego1 ; mean out ; B split {eh, el}
__global__ void __launch_bounds__(256) gather2_kernel(float* __restrict__ dout) {
    __shared__ float part[2][64];
    int w = threadIdx.x >> 5, lane = threadIdx.x & 31;
    int rloc = w >> 2, sub = w & 3;
    int r = blockIdx.x * 2 + rloc;
    int e = (sub & 1) * 32 + lane;
    float eg2 = gather_split(g_cntN, g_ellN, g_ego1, part, r, rloc, sub, e);
    if (!(sub >> 1)) {
        g_ego2[r * E + e] = eg2;
        dout[r * E + e] = 0.5f * (g_ego0[r * E + e] + g_ego1[r * E + e]);
        __half h, l;
        split2h(eg2, h, l);
        __half* b = &g_B[r * KB + e];
        b[0] = h; b[64] = l;
    }
}

// K4: z = ego2 + 0.5*A@ego2 ; store z ; A split {zh, zh}
__global__ void __launch_bounds__(256) gatherA_kernel() {
    __shared__ float part[2][64];
    int w = threadIdx.x >> 5, lane = threadIdx.x & 31;
    int rloc = w >> 2, sub = w & 3;
    int r = blockIdx.x * 2 + rloc;
    int e = (sub & 1) * 32 + lane;
    float acc = gather_split(g_cntA, g_ellA, g_ego2, part, r, rloc, sub, e);
    if (!(sub >> 1)) {
        float z = 0.5f * acc + g_ego2[r * E + e];
        g_z[r * E + e] = z;
        __half h = __float2half_rn(z);
        __half* a = &g_A[r * KB + e];
        a[0] = h; a[64] = h;
    }
}

// K5: Q/K projection (weights in regs) — 192 blocks x 32 rows
__global__ void __launch_bounds__(256, 1) qk_kernel(const float* __restrict__ bq,
                                                    const float* __restrict__ bk) {
    __shared__ u64 xs[32 * E2];
    int t = threadIdx.x;
    u64 wq[E2], wk[E2];
#pragma unroll
    for (int i = 0; i < E2; i++) { wq[i] = g_WqT[i * DQK + t]; wk[i] = g_WkT[i * DQK + t]; }
    float rbq = bq[t], rbk = bk[t];
    const u64* eg = (const u64*)g_ego2;
    int r0 = blockIdx.x * 32;
    for (int i = t; i < 32 * E2; i += 256) xs[i] = eg[r0 * E2 + i];
    __syncthreads();
    for (int rr = 0; rr < 32; rr++) {
        const ulonglong2* xp = (const ulonglong2*)&xs[rr * E2];
        u64 aq = 0ULL, ak = 0ULL;
#pragma unroll
        for (int e2 = 0; e2 < E2; e2 += 2) {
            ulonglong2 xv = xp[e2 >> 1];
            aq = ffma2(wq[e2], xv.x, aq);
            ak = ffma2(wk[e2], xv.x, ak);
            aq = ffma2(wq[e2 + 1], xv.y, aq);
            ak = ffma2(wk[e2 + 1], xv.y, ak);
        }
        float2 q2 = up2(aq), k2 = up2(ak);
        g_Q[(r0 + rr) * DQK + t] = q2.x + q2.y + rbq;
        g_K[(r0 + rr) * DQK + t] = k2.x + k2.y + rbk;
    }
}

// K6: mma.sync fp16 approx sim (K=128) + per-row top-10 (per j-third)
// unchanged from round 12
__global__ void __launch_bounds__(256, 1) simtopk_mma_kernel() {
    extern __shared__ char sm[];
    unsigned sA = s2u(sm);
    unsigned sB0 = sA + 128 * APITCH;
    int tid = threadIdx.x, w = tid >> 5, lane = tid & 31;
    int rg = blockIdx.x / 3, jthird = blockIdx.x - rg * 3;
    int r0 = rg * 128, jb0 = jthird * JTHIRD;

    {
        unsigned dst = sB0;
        const char* src = (const char*)g_B + (size_t)jb0 * (KB * 2);
        for (int i = tid; i < CHUNK * 16; i += 256) {
            int r = i >> 4, c = i & 15;
            asm volatile("cp.async.cg.shared.global [%0], [%1], 16;"
                         :: "r"(dst + r * APITCH + c * 16), "l"(src + r * (KB * 2) + c * 16));
        }
        asm volatile("cp.async.commit_group;");
    }
    {
        const u64* asrc = (const u64*)(g_A + (size_t)r0 * KB);
        for (int i = tid; i < 128 * 32; i += 256) {
            int r = i >> 5, c = i & 31;
            *(u64*)(sm + r * APITCH + c * 8) = asrc[i];
        }
    }
    __syncthreads();

    unsigned af[8][4];
    {
        unsigned ab = sA + (w * 16 + (lane & 15)) * APITCH + ((lane >> 4) << 4);
#pragma unroll
        for (int kt = 0; kt < 8; kt++)
            asm volatile("ldmatrix.sync.aligned.m8n8.x4.shared.b16 {%0,%1,%2,%3}, [%4];"
                : "=r"(af[kt][0]), "=r"(af[kt][1]), "=r"(af[kt][2]), "=r"(af[kt][3])
                : "r"(ab + kt * 32));
    }

    float tv0[TOPS], tv1[TOPS]; int ti0[TOPS], ti1[TOPS];
#pragma unroll
    for (int q = 0; q < TOPS; q++) {
        tv0[q] = -3.0e38f; tv1[q] = -3.0e38f; ti0[q] = 0; ti1[q] = 0;
    }

    for (int cc = 0; cc < NCHUNK; cc++) {
        if (cc + 1 < NCHUNK) {
            unsigned dst = sB0 + ((cc + 1) & 1) * BBYTES;
            const char* src = (const char*)g_B + (size_t)(jb0 + (cc + 1) * CHUNK) * (KB * 2);
            for (int i = tid; i < CHUNK * 16; i += 256) {
                int r = i >> 4, c = i & 15;
                asm volatile("cp.async.cg.shared.global [%0], [%1], 16;"
                             :: "r"(dst + r * APITCH + c * 16), "l"(src + r * (KB * 2) + c * 16));
            }
            asm volatile("cp.async.commit_group;");
            asm volatile("cp.async.wait_group 1;");
        } else {
            asm volatile("cp.async.wait_group 0;");
        }
        __syncthreads();
        unsigned sBc = sB0 + (cc & 1) * BBYTES;
        int j0 = jb0 + cc * CHUNK;
        for (int jt = 0; jt < 8; jt += 2) {
            float dA0 = 0, dA1 = 0, dA2 = 0, dA3 = 0;
            float dB0 = 0, dB1 = 0, dB2 = 0, dB3 = 0;
            unsigned ba = sBc + (jt * 8 + (lane & 7)) * APITCH + ((lane >> 3) & 1) * 16;
            unsigned bb = ba + 8 * APITCH;
#pragma unroll
            for (int kt = 0; kt < 8; kt++) {
                unsigned p0, p1, q0, q1;
                asm volatile("ldmatrix.sync.aligned.m8n8.x2.shared.b16 {%0,%1}, [%2];"
                             : "=r"(p0), "=r"(p1) : "r"(ba + kt * 32));
                asm volatile("ldmatrix.sync.aligned.m8n8.x2.shared.b16 {%0,%1}, [%2];"
                             : "=r"(q0), "=r"(q1) : "r"(bb + kt * 32));
                asm volatile("mma.sync.aligned.m16n8k16.row.col.f32.f16.f16.f32 "
                    "{%0,%1,%2,%3}, {%4,%5,%6,%7}, {%8,%9}, {%0,%1,%2,%3};"
                    : "+f"(dA0), "+f"(dA1), "+f"(dA2), "+f"(dA3)
                    : "r"(af[kt][0]), "r"(af[kt][1]), "r"(af[kt][2]), "r"(af[kt][3]),
                      "r"(p0), "r"(p1));
                asm volatile("mma.sync.aligned.m16n8k16.row.col.f32.f16.f16.f32 "
                    "{%0,%1,%2,%3}, {%4,%5,%6,%7}, {%8,%9}, {%0,%1,%2,%3};"
                    : "+f"(dB0), "+f"(dB1), "+f"(dB2), "+f"(dB3)
                    : "r"(af[kt][0]), "r"(af[kt][1]), "r"(af[kt][2]), "r"(af[kt][3]),
                      "r"(q0), "r"(q1));
            }
            int jcA = j0 + jt * 8 + (lane & 3) * 2;
            int jcB = jcA + 8;
            top_ins(dA0, jcA, tv0, ti0);     top_ins(dA1, jcA + 1, tv0, ti0);
            top_ins(dA2, jcA, tv1, ti1);     top_ins(dA3, jcA + 1, tv1, ti1);
            top_ins(dB0, jcB, tv0, ti0);     top_ins(dB1, jcB + 1, tv0, ti0);
            top_ins(dB2, jcB, tv1, ti1);     top_ins(dB3, jcB + 1, tv1, ti1);
        }
        __syncthreads();
    }

    float* mv = (float*)sm;
    int*   mi = (int*)(sm + 128 * MPITCH * 4);
    int rb = w * 16 + (lane >> 2);
    int slot = (lane & 3) * TOPS;
#pragma unroll
    for (int q = 0; q < TOPS; q++) {
        mv[rb * MPITCH + slot + q] = tv0[q];        mi[rb * MPITCH + slot + q] = ti0[q];
        mv[(rb + 8) * MPITCH + slot + q] = tv1[q];  mi[(rb + 8) * MPITCH + slot + q] = ti1[q];
    }
    __syncthreads();
    if (tid < 128) {
        for (int sel = 0; sel < TOPS; sel++) {
            float best = -3.2e38f; int bs = 0;
            for (int m = 0; m < 40; m++) {
                float vv = mv[tid * MPITCH + m];
                if (vv > best) { best = vv; bs = m; }
            }
            mv[tid * MPITCH + bs] = -3.2e38f;
            g_candi[(r0 + tid) * NCAND + jthird * TOPS + sel] = mi[tid * MPITCH + bs];
        }
    }
}

// K7: exact rescore (register top-5) + attention + V proj ; resets counters
__global__ void __launch_bounds__(256, 1) attn_kernel(const float* __restrict__ bv,
                                                      float* __restrict__ out_att) {
    __shared__ __align__(16) float ws[32 * E];
    __shared__ int exi[8][NCAND];
    int t = threadIdx.x, lane = t & 31, w = t >> 5;
    int n0 = blockIdx.x * 32;

    {
        int i = blockIdx.x * 256 + t;
        if (i < NN) g_cntN[i] = 0;
        else if (i < 2 * NN) g_cntA[i - NN] = 0;
    }

    for (int i = 0; i < 4; i++) {
        int nl = i * 8 + w;
        int n = n0 + nl;
        int cid = g_candi[n * NCAND + (lane < NCAND ? lane : 0)];
        if (lane < NCAND) exi[w][lane] = cid;
        __syncwarp();
        float zl0 = g_z[n * E + lane];
        float zl1 = g_z[n * E + lane + 32];
        float sv[NCAND];
#pragma unroll
        for (int m = 0; m < NCAND; m++) {
            int id = __shfl_sync(0xffffffffu, cid, m);
            const float* ep = &g_ego2[id * E];
            float s = zl0 * ep[lane] + zl1 * ep[lane + 32];
#pragma unroll
            for (int o = 16; o > 0; o >>= 1)
                s += __shfl_xor_sync(0xffffffffu, s, o);
            sv[m] = s;   // every lane holds full score vector
        }
        // register top-5 via used-bitmask scan
        int idx[TOPK];
        unsigned used = 0;
#pragma unroll
        for (int sel = 0; sel < TOPK; sel++) {
            float best = -3.2e38f; int bs = 0;
#pragma unroll
            for (int m = 0; m < NCAND; m++)
                if (!((used >> m) & 1u) && sv[m] > best) { best = sv[m]; bs = m; }
            used |= (1u << bs);
            idx[sel] = exi[w][bs];
        }
        float q[8];
#pragma unroll
        for (int j = 0; j < 8; j++) q[j] = g_Q[n * DQK + j * 32 + lane];
        float p[TOPK];
#pragma unroll
        for (int k = 0; k < TOPK; k++) {
            const float* kp = &g_K[idx[k] * DQK];
            float s = 0.0f;
#pragma unroll
            for (int j = 0; j < 8; j++) s += q[j] * kp[j * 32 + lane];
            p[k] = s;
        }
#pragma unroll
        for (int k = 0; k < TOPK; k++)
#pragma unroll
            for (int o = 16; o > 0; o >>= 1)
                p[k] += __shfl_xor_sync(0xffffffffu, p[k], o);
        float mx = -3.0e38f;
#pragma unroll
        for (int k = 0; k < TOPK; k++) { p[k] *= 0.0625f; mx = fmaxf(mx, p[k]); }
        float den = 0.0f;
#pragma unroll
        for (int k = 0; k < TOPK; k++) { p[k] = __expf(p[k] - mx); den += p[k]; }
        float inv = 1.0f / den;
        float a0 = 0.0f, a1 = 0.0f;
#pragma unroll
        for (int k = 0; k < TOPK; k++) {
            float a = p[k] * inv;
            const float* ep = &g_ego2[idx[k] * E];
            a0 += a * ep[lane];
            a1 += a * ep[lane + 32];
        }
        ws[nl * E + lane] = a0;
        ws[nl * E + lane + 32] = a1;
    }
    __syncthreads();
    u64 wv[E2];
#pragma unroll
    for (int i = 0; i < E2; i++) wv[i] = g_WvT[i * DQK + t];
    float rbv = bv[t];
    for (int rr = 0; rr < 32; rr++) {
        const ulonglong2* xp = (const ulonglong2*)&ws[rr * E];
        u64 av = 0ULL;
#pragma unroll
        for (int e2 = 0; e2 < E2; e2 += 2) {
            ulonglong2 xv = xp[e2 >> 1];
            av = ffma2(wv[e2], xv.x, av);
            av = ffma2(wv[e2 + 1], xv.y, av);
        }
        float2 fv = up2(av);
        out_att[(n0 + rr) * DQK + t] = fv.x + fv.y + rbv;
    }
}

extern "C" void kernel_launch(void* const* d_in, const int* in_sizes, int n_in,
                              void* d_out, int out_size) {
    const float* user = (const float*)d_in[0];
    const float* item = (const float*)d_in[1];
    const int* nr = (const int*)d_in[2];
    const int* nc = (const int*)d_in[3];
    const float* nv = (const float*)d_in[4];
    const int* ar = (const int*)d_in[5];
    const int* ac = (const int*)d_in[6];
    const float* av = (const float*)d_in[7];
    const float* Wq = (const float*)d_in[8];
    const float* bq = (const float*)d_in[9];
    const float* Wk = (const float*)d_in[10];
    const float* bk = (const float*)d_in[11];
    const float* Wv = (const float*)d_in[12];
    const float* bv = (const float*)d_in[13];
    int nnzN = in_sizes[2];
    int nnzA = in_sizes[5];
    float* out = (float*)d_out;

    const int TPB = 256;
    int total1 = NN * E + 3 * E2 * DQK + nnzN + nnzA;
    prep_place_kernel<<<(total1 + TPB - 1) / TPB, TPB>>>(
        user, item, nr, nc, nv, nnzN, ar, ac, av, nnzA, Wq, Wk, Wv);

    gather1_kernel<<<NN / 2, TPB>>>();
    gather2_kernel<<<NN / 2, TPB>>>(out);
    gatherA_kernel<<<NN / 2, TPB>>>();
    qk_kernel<<<NN / 32, TPB>>>(bq, bk);

    int smem_mma = 128 * APITCH + 2 * BBYTES;   // 69632
    cudaFuncSetAttribute(simtopk_mma_kernel,
                         cudaFuncAttributeMaxDynamicSharedMemorySize, smem_mma);
    simtopk_mma_kernel<<<(NN / 128) * 3, TPB, smem_mma>>>();

    attn_kernel<<<NN / 32, TPB>>>(bv, out + NN * E);
}